// round 1
// baseline (speedup 1.0000x reference)
#include <cuda_runtime.h>

#define Hh 64
#define Ww 64
#define CIN 512
#define OCN 128
#define NPIX 4096
#define CHUNK 8

// Scratch (no allocations allowed): transposed weights, per-(conv,b,oc) sums, channel vec
__device__ float g_Wt[2 * CIN * 9 * OCN];   // [conv][ic][tap][oc]  (~4.5 MB)
__device__ float g_sums[2 * 2 * OCN];       // [conv][b][oc]
__device__ float g_cc[2 * 512];             // [b][ch]

__device__ __forceinline__ unsigned long long pack2(float v) {
    unsigned long long r;
    int iv = __float_as_int(v);
    asm("mov.b64 %0, {%1, %1};" : "=l"(r) : "r"(iv));
    return r;
}
__device__ __forceinline__ void fma2(unsigned long long& acc, unsigned long long a,
                                     unsigned long long b) {
    asm("fma.rn.f32x2 %0, %1, %2, %0;" : "+l"(acc) : "l"(a), "l"(b));
}

// ---------------------------------------------------------------------------
// Kernel 1: transpose weights to [conv][ic][tap][oc]; zero the sum scratch.
// ---------------------------------------------------------------------------
__global__ void prep_kernel(const float* __restrict__ W2, const float* __restrict__ W4) {
    int idx = blockIdx.x * blockDim.x + threadIdx.x;
    if (idx < 2 * 2 * OCN) g_sums[idx] = 0.f;
    const int PER = OCN * CIN * 9;  // 589824
    if (idx < 2 * PER) {
        int conv = idx / PER;
        int r = idx - conv * PER;            // = oc*4608 + ic*9 + tap
        int oc = r / (CIN * 9);
        int s = r - oc * (CIN * 9);
        int ic = s / 9;
        int tap = s - ic * 9;
        const float* Wsrc = conv ? W4 : W2;
        g_Wt[conv * PER + (ic * 9 + tap) * OCN + oc] = Wsrc[r];
    }
}

// ---------------------------------------------------------------------------
// Kernel 2: dilated conv (512->128, 3x3, dilation 3 or 7) + bias + relu +
// spatial-sum reduction. One block per (row, conv, batch). 256 threads.
// Thread tile: 8 oc (as 4 f32x2 pairs) x 4 px.
// ---------------------------------------------------------------------------
__global__ void __launch_bounds__(256, 2)
conv_reduce_kernel(const float* __restrict__ x, const float* __restrict__ b2,
                   const float* __restrict__ b4) {
    __shared__ float sX[CHUNK][3][80];      // 3 input rows, center at col 7 (pad for d<=7)
    __shared__ float sW[CHUNK][9][OCN];     // [ic][tap][oc]
    __shared__ float sRed[OCN];

    int row  = blockIdx.x;   // output row 0..63
    int conv = blockIdx.y;   // 0: W2,d=3   1: W4,d=7
    int bb   = blockIdx.z;   // batch
    int d = conv ? 7 : 3;
    const float* bias = conv ? b4 : b2;
    const float* xb = x + bb * CIN * NPIX;
    const float* Wt = g_Wt + conv * (OCN * CIN * 9);

    int tid = threadIdx.x;
    for (int i = tid; i < CHUNK * 3 * 80; i += 256) ((float*)sX)[i] = 0.f;  // zero pads
    if (tid < OCN) sRed[tid] = 0.f;

    int oc0 = (tid & 15) * 8;
    int px0 = (tid >> 4) * 4;

    unsigned long long acc[4][4];  // [oc-pair][px], packed f32x2 (zero bits == (0.f,0.f))
#pragma unroll
    for (int j = 0; j < 4; ++j)
#pragma unroll
        for (int p = 0; p < 4; ++p) acc[j][p] = 0ull;

#pragma unroll 1
    for (int ic0 = 0; ic0 < CIN; ic0 += CHUNK) {
        __syncthreads();
        // weights: 8*9*128 floats contiguous in g_Wt -> coalesced float4
        const float4* wsrc = (const float4*)(Wt + ic0 * 9 * OCN);
        float4* wdst = (float4*)&sW[0][0][0];
#pragma unroll
        for (int i = 0; i < 9; ++i) wdst[tid + i * 256] = wsrc[tid + i * 256];
        // x: 8 ic x 3 rows x 64 cols, rows y-d, y, y+d (zero outside)
        for (int i = tid; i < CHUNK * 3 * 64; i += 256) {
            int ic_l = i / 192;
            int rem = i - ic_l * 192;
            int r = rem >> 6;
            int col = rem & 63;
            int yy = row + (r - 1) * d;
            float v = 0.f;
            if (yy >= 0 && yy < Hh) v = xb[(ic0 + ic_l) * NPIX + yy * Ww + col];
            sX[ic_l][r][7 + col] = v;
        }
        __syncthreads();

#pragma unroll 1
        for (int ic_l = 0; ic_l < CHUNK; ++ic_l) {
#pragma unroll
            for (int r = 0; r < 3; ++r) {
                const float* xrow = &sX[ic_l][r][7 + px0];
#pragma unroll
                for (int c = 0; c < 3; ++c) {
                    const unsigned long long* wp =
                        (const unsigned long long*)&sW[ic_l][r * 3 + c][oc0];
                    unsigned long long w0 = wp[0], w1 = wp[1], w2 = wp[2], w3 = wp[3];
                    int off = (c - 1) * d;
#pragma unroll
                    for (int p = 0; p < 4; ++p) {
                        unsigned long long xx = pack2(xrow[p + off]);
                        fma2(acc[0][p], w0, xx);
                        fma2(acc[1][p], w1, xx);
                        fma2(acc[2][p], w2, xx);
                        fma2(acc[3][p], w3, xx);
                    }
                }
            }
        }
    }

    __syncthreads();
    // bias + relu + reduce over this thread's 4 px, then over the block, then global
#pragma unroll
    for (int j = 0; j < 4; ++j) {
        float bx = bias[oc0 + 2 * j];
        float by = bias[oc0 + 2 * j + 1];
        float sx = 0.f, sy = 0.f;
#pragma unroll
        for (int p = 0; p < 4; ++p) {
            float2 v = *(float2*)&acc[j][p];
            sx += fmaxf(v.x + bx, 0.f);
            sy += fmaxf(v.y + by, 0.f);
        }
        atomicAdd(&sRed[oc0 + 2 * j], sx);
        atomicAdd(&sRed[oc0 + 2 * j + 1], sy);
    }
    __syncthreads();
    if (tid < OCN) atomicAdd(&g_sums[(conv * 2 + bb) * OCN + tid], sRed[tid]);
}

// ---------------------------------------------------------------------------
// Kernel 3: tiny GEMV chain. The whole attention machinery collapses:
//   g[conv][b]  = Wd @ mean(a_conv)            (512 <- 128)
//   zsum[b]     = Wcc @ (g[0]+g[1]) + 2*bcc    (256 <- 512)
//   cc[b]       = Wd2 @ zsum                   (512 <- 256)
// ---------------------------------------------------------------------------
__global__ void head_kernel(const float* __restrict__ Wd, const float* __restrict__ Wcc,
                            const float* __restrict__ bcc, const float* __restrict__ Wd2) {
    __shared__ float m[2][2][OCN];
    __shared__ float g1[2][2][512];
    __shared__ float gs[2][512];
    __shared__ float zs[2][256];
    int tid = threadIdx.x;  // 512

    if (tid < 512) ((float*)m)[tid] = g_sums[tid] * (1.f / NPIX);
    __syncthreads();

    for (int i = tid; i < 2048; i += 512) {
        int conv = i >> 10;
        int b = (i >> 9) & 1;
        int o = i & 511;
        const float* w = Wd + o * OCN;
        const float* mm = m[conv][b];
        float s = 0.f;
#pragma unroll 8
        for (int c = 0; c < OCN; ++c) s += w[c] * mm[c];
        g1[conv][b][o] = s;
    }
    __syncthreads();
    for (int i = tid; i < 1024; i += 512) {
        int b = i >> 9;
        int o = i & 511;
        gs[b][o] = g1[0][b][o] + g1[1][b][o];
    }
    __syncthreads();
    if (tid < 512) {
        int b = tid >> 8;
        int o = tid & 255;
        const float* w = Wcc + o * 512;
        float s = 2.f * bcc[o];
#pragma unroll 8
        for (int c = 0; c < 512; ++c) s += w[c] * gs[b][c];
        zs[b][o] = s;
    }
    __syncthreads();
    for (int i = tid; i < 1024; i += 512) {
        int b = i >> 9;
        int o = i & 511;
        const float* w = Wd2 + o * 256;
        float s = 0.f;
#pragma unroll 8
        for (int c = 0; c < 256; ++c) s += w[c] * zs[b][c];
        g_cc[b * 512 + o] = s;
    }
}

// ---------------------------------------------------------------------------
// Kernel 4: out[b,ch,h,w] = x[b,ch,h,w] + cc[b,ch]   (vectorized float4)
// ---------------------------------------------------------------------------
__global__ void add_kernel(const float* __restrict__ x, float* __restrict__ out) {
    int idx = blockIdx.x * blockDim.x + threadIdx.x;
    const int TOT4 = 2 * 512 * NPIX / 4;  // 1048576
    if (idx < TOT4) {
        int row = idx >> 10;  // 1024 float4 per (b,ch)
        float c = g_cc[row];
        float4 v = ((const float4*)x)[idx];
        v.x += c; v.y += c; v.z += c; v.w += c;
        ((float4*)out)[idx] = v;
    }
}

extern "C" void kernel_launch(void* const* d_in, const int* in_sizes, int n_in,
                              void* d_out, int out_size) {
    const float* x   = (const float*)d_in[0];
    const float* W2  = (const float*)d_in[3];
    const float* b2  = (const float*)d_in[4];
    const float* W4  = (const float*)d_in[7];
    const float* b4  = (const float*)d_in[8];
    const float* Wd  = (const float*)d_in[9];
    const float* Wcc = (const float*)d_in[10];
    const float* bcc = (const float*)d_in[11];
    const float* Wd2 = (const float*)d_in[12];
    float* out = (float*)d_out;

    prep_kernel<<<(2 * OCN * CIN * 9 + 255) / 256, 256>>>(W2, W4);
    dim3 grid(Hh, 2, 2);
    conv_reduce_kernel<<<grid, 256>>>(x, b2, b4);
    head_kernel<<<1, 512>>>(Wd, Wcc, bcc, Wd2);
    add_kernel<<<(2 * 512 * NPIX / 4 + 255) / 256, 256>>>(x, out);
}